// round 9
// baseline (speedup 1.0000x reference)
#include <cuda_runtime.h>
#include <cuda_fp16.h>
#include <math.h>
#include <stdint.h>

#define DE    100
#define DR    100
#define RK    40
#define NENT  10000
#define BATCH 128
#define KDIM  1600          // RK*RK — single-segment fp16 K
#define MN    10000         // DE*DE
#define FSTR  (DE*RK)       // 4000
#define KBIG  1600
#define BKC   64            // fp16 per K-chunk (128 B row)
#define NCHUNK (KBIG/BKC)   // 25
#define NSTG  3

// GEMM tile (occ-2 sizing)
#define BM 128
#define BN 128
#define STAGE_A (BM*128)
#define STAGE_B (BN*128)
#define STAGE_BYTES (STAGE_A+STAGE_B) // 32768 B
#define SMEM_TOTAL (NSTG*STAGE_BYTES) // 98304 B/CTA -> 2 CTAs/SM
#define ERS 136

// ---------- device scratch ----------
__device__ __half g_Abig[(size_t)MN * KBIG];  // 32 MB
__device__ __half g_Bbig[(size_t)MN * KBIG];  // 32 MB
__device__ float g_rbn  [BATCH * DR];
__device__ float g_e1bn [BATCH * DE];
__device__ float g_e2bn [BATCH * DE];
__device__ float g_u0   [BATCH * KDIM];       // 819 KB
__device__ float g_v1   [BATCH * KDIM];
__device__ float g_v3   [BATCH * KDIM];
__device__ float g_f2p  [KDIM * DE];          // 640 KB permuted f2
__device__ float g_wout [BATCH * DE];
__device__ float g_woutbn[BATCH * DE];
__device__ float g_scores[BATCH * NENT];

// ==================== helpers ====================
__device__ __forceinline__ uint32_t smem_u32(const void* p) {
    uint32_t a;
    asm("{ .reg .u64 t; cvta.to.shared.u64 t, %1; cvt.u32.u64 %0, t; }" : "=r"(a) : "l"(p));
    return a;
}
__device__ __forceinline__ void cp16(uint32_t dst, const void* src) {
    asm volatile("cp.async.cg.shared.global [%0], [%1], 16;\n" :: "r"(dst), "l"(src) : "memory");
}
__device__ __forceinline__ void cp_commit() {
    asm volatile("cp.async.commit_group;" ::: "memory");
}
template <int N>
__device__ __forceinline__ void cp_wait() {
    asm volatile("cp.async.wait_group %0;" :: "n"(N) : "memory");
}
__device__ __forceinline__ void ldsm_x4(uint32_t& r0, uint32_t& r1, uint32_t& r2, uint32_t& r3, uint32_t addr) {
    asm volatile("ldmatrix.sync.aligned.m8n8.x4.shared.b16 {%0,%1,%2,%3}, [%4];"
                 : "=r"(r0), "=r"(r1), "=r"(r2), "=r"(r3) : "r"(addr));
}
__device__ __forceinline__ void mma16816(float* c, const uint32_t* a, uint32_t b0, uint32_t b1) {
    asm volatile(
        "mma.sync.aligned.m16n8k16.row.col.f32.f16.f16.f32 "
        "{%0,%1,%2,%3}, {%4,%5,%6,%7}, {%8,%9}, {%0,%1,%2,%3};"
        : "+f"(c[0]), "+f"(c[1]), "+f"(c[2]), "+f"(c[3])
        : "r"(a[0]), "r"(a[1]), "r"(a[2]), "r"(a[3]), "r"(b0), "r"(b1));
}

// ---------------------------------------------------------------------
// pair_contract v2 (unchanged from R8).
__global__ __launch_bounds__(256) void pair_contract(const float* __restrict__ X,
                                                     const float* __restrict__ Y,
                                                     int swap)
{
    __shared__ float Xs[RK][44];
    __shared__ float Ys[RK][44];
    __half* out = swap ? g_Bbig : g_Abig;
    const int p = blockIdx.x / DE;
    const int q = blockIdx.x % DE;
    const int t = threadIdx.x;

    for (int lin = t; lin < RK * RK; lin += 256) {
        int u = lin / RK, w = lin % RK;
        Xs[u][w] = X[u * FSTR + p * RK + w];
        Ys[u][w] = Y[u * FSTR + q * RK + w];
    }
    __syncthreads();

    if (t < 200) {
        const int r0 = (t / 10) * 2;
        const int s0 = (t % 10) * 4;
        float tr[2][4];
#pragma unroll
        for (int i = 0; i < 2; i++)
#pragma unroll
            for (int j = 0; j < 4; j++) tr[i][j] = 0.f;
#pragma unroll
        for (int b = 0; b < RK; b++) {
            float x0 = Xs[r0][b];
            float x1 = Xs[r0 + 1][b];
            float4 y = *reinterpret_cast<const float4*>(&Ys[b][s0]);
            tr[0][0] += x0 * y.x; tr[0][1] += x0 * y.y;
            tr[0][2] += x0 * y.z; tr[0][3] += x0 * y.w;
            tr[1][0] += x1 * y.x; tr[1][1] += x1 * y.y;
            tr[1][2] += x1 * y.z; tr[1][3] += x1 * y.w;
        }
        __half* rb = out + (size_t)blockIdx.x * KBIG;
        if (swap == 0) {
#pragma unroll
            for (int i = 0; i < 2; i++) {
                __half2 h0 = __floats2half2_rn(tr[i][0], tr[i][1]);
                __half2 h1 = __floats2half2_rn(tr[i][2], tr[i][3]);
                uint2 v = make_uint2(*(uint32_t*)&h0, *(uint32_t*)&h1);
                *reinterpret_cast<uint2*>(rb + (r0 + i) * RK + s0) = v;
            }
        } else {
#pragma unroll
            for (int j = 0; j < 4; j++) {
                __half2 h = __floats2half2_rn(tr[0][j], tr[1][j]);
                *reinterpret_cast<__half2*>(rb + (s0 + j) * RK + r0) = h;
            }
        }
    }
}

// ---------------------------------------------------------------------
// tn_gemm (unchanged from R8): 128x128 tile, occ 2, smem epilogue.
__global__ void __launch_bounds__(256, 2) tn_gemm(float* __restrict__ Wout)
{
    extern __shared__ __align__(1024) char smem[];
    const uint32_t sb = smem_u32(smem);
    const int tid  = threadIdx.x;
    const int lane = tid & 31;
    const int wid  = tid >> 5;
    const int wm   = wid >> 2;
    const int wn   = wid & 3;
    const int m0 = blockIdx.y * BM;
    const int n0 = blockIdx.x * BN;
    const __half* __restrict__ A = g_Abig;
    const __half* __restrict__ B = g_Bbig;

    float acc[4][4][4];
#pragma unroll
    for (int i = 0; i < 4; i++)
#pragma unroll
        for (int j = 0; j < 4; j++)
#pragma unroll
            for (int k = 0; k < 4; k++) acc[i][j][k] = 0.f;

    auto load_stage = [&](int ck, int stg) {
        uint32_t sA = sb + stg * STAGE_BYTES;
        uint32_t sB = sA + STAGE_A;
#pragma unroll
        for (int i = 0; i < 4; i++) {
            int q = tid + i * 256;
            int row = q >> 3, seg = q & 7;
            int gm = m0 + row; if (gm > MN - 1) gm = MN - 1;
            cp16(sA + row * 128 + ((seg * 16) ^ ((row & 7) << 4)),
                 A + (size_t)gm * KBIG + ck * BKC + seg * 8);
        }
#pragma unroll
        for (int i = 0; i < 4; i++) {
            int q = tid + i * 256;
            int row = q >> 3, seg = q & 7;
            int gn = n0 + row; if (gn > MN - 1) gn = MN - 1;
            cp16(sB + row * 128 + ((seg * 16) ^ ((row & 7) << 4)),
                 B + (size_t)gn * KBIG + ck * BKC + seg * 8);
        }
        cp_commit();
    };

    const int aq = lane >> 3;
    const int arow = ((aq & 1) << 3) + (lane & 7);
    const int akb  = (aq >> 1) << 4;
    const int brow = ((aq >> 1) << 3) + (lane & 7);
    const int bkb  = (aq & 1) << 4;
    const int xm = (lane & 7) << 4;

    uint32_t aoff[4], boff[2];
#pragma unroll
    for (int mi = 0; mi < 4; mi++) aoff[mi] = (wm * 64 + mi * 16 + arow) * 128;
#pragma unroll
    for (int ng = 0; ng < 2; ng++) boff[ng] = (wn * 32 + ng * 16 + brow) * 128;

    load_stage(0, 0);
    load_stage(1, 1);

    for (int c = 0; c < NCHUNK; c++) {
        if (c < NCHUNK - 1) cp_wait<1>(); else cp_wait<0>();
        __syncthreads();
        if (c + 2 < NCHUNK) load_stage(c + 2, (c + 2) % NSTG);

        uint32_t sA = sb + (c % NSTG) * STAGE_BYTES;
        uint32_t sB = sA + STAGE_A;

#pragma unroll
        for (int ks = 0; ks < 4; ks++) {
            const uint32_t kAx = (uint32_t)((ks * 32 + akb) ^ xm);
            const uint32_t kBx = (uint32_t)((ks * 32 + bkb) ^ xm);
            uint32_t a[4][4];
#pragma unroll
            for (int mi = 0; mi < 4; mi++)
                ldsm_x4(a[mi][0], a[mi][1], a[mi][2], a[mi][3], sA + aoff[mi] + kAx);
#pragma unroll
            for (int ng = 0; ng < 2; ng++) {
                uint32_t b0, b1, b2, b3;
                ldsm_x4(b0, b1, b2, b3, sB + boff[ng] + kBx);
#pragma unroll
                for (int mi = 0; mi < 4; mi++) {
                    mma16816(acc[mi][ng * 2 + 0], a[mi], b0, b1);
                    mma16816(acc[mi][ng * 2 + 1], a[mi], b2, b3);
                }
            }
        }
        __syncthreads();
    }

    float* buf = reinterpret_cast<float*>(smem);
    const int rl = wm * 64 + (lane >> 2);
    const int cl = wn * 32 + 2 * (lane & 3);
#pragma unroll
    for (int mi = 0; mi < 4; mi++) {
        int r = rl + mi * 16;
#pragma unroll
        for (int nj = 0; nj < 4; nj++) {
            *reinterpret_cast<float2*>(&buf[r * ERS + cl + nj * 8]) =
                make_float2(acc[mi][nj][0], acc[mi][nj][1]);
            *reinterpret_cast<float2*>(&buf[(r + 8) * ERS + cl + nj * 8]) =
                make_float2(acc[mi][nj][2], acc[mi][nj][3]);
        }
    }
    __syncthreads();
    for (int idx = tid; idx < 128 * 32; idx += 256) {
        int r  = idx >> 5;
        int c4 = (idx & 31) << 2;
        int gm = m0 + r, gn = n0 + c4;
        if (gm < MN && gn < MN) {
            float4 v = make_float4(buf[r * ERS + c4], buf[r * ERS + c4 + 1],
                                   buf[r * ERS + c4 + 2], buf[r * ERS + c4 + 3]);
            *reinterpret_cast<float4*>(Wout + (size_t)gm * MN + gn) = v;
        }
    }
}

// ---------------------------------------------------------------------
// bn3 (unchanged): fused BatchNorm for r / e1 / e2.
__global__ __launch_bounds__(128) void bn3_kernel(const float* __restrict__ R,
                                                  const float* __restrict__ E,
                                                  const int* __restrict__ r_idx,
                                                  const int* __restrict__ e_idx1,
                                                  const int* __restrict__ e_idx2,
                                                  const float* __restrict__ bnr_g,
                                                  const float* __restrict__ bnr_b,
                                                  const float* __restrict__ bne_g,
                                                  const float* __restrict__ bne_b)
{
    const int bid = blockIdx.x;
    const int b   = threadIdx.x;
    const float* table; const int* idx; const float* gamma; const float* beta;
    float* out; int col;
    if (bid < DR)            { table = R; idx = r_idx;  gamma = bnr_g; beta = bnr_b; out = g_rbn;  col = bid; }
    else if (bid < DR + DE)  { table = E; idx = e_idx1; gamma = bne_g; beta = bne_b; out = g_e1bn; col = bid - DR; }
    else                     { table = E; idx = e_idx2; gamma = bne_g; beta = bne_b; out = g_e2bn; col = bid - DR - DE; }

    float x = table[(size_t)idx[b] * DE + col];

    __shared__ float ssum[4], ssq[4];
    __shared__ float smu, srs;
    float s = x, sq = x * x;
#pragma unroll
    for (int o = 16; o > 0; o >>= 1) {
        s  += __shfl_down_sync(0xffffffffu, s, o);
        sq += __shfl_down_sync(0xffffffffu, sq, o);
    }
    int w = b >> 5, l = b & 31;
    if (l == 0) { ssum[w] = s; ssq[w] = sq; }
    __syncthreads();
    if (b == 0) {
        float ts = ssum[0] + ssum[1] + ssum[2] + ssum[3];
        float tq = ssq[0]  + ssq[1]  + ssq[2]  + ssq[3];
        float mu  = ts * (1.f / BATCH);
        float var = tq * (1.f / BATCH) - mu * mu;
        smu = mu;
        srs = rsqrtf(var + 1e-5f);
    }
    __syncthreads();
    out[b * DE + col] = gamma[col] * (x - smu) * srs + beta[col];
}

// ---------------------------------------------------------------------
__global__ __launch_bounds__(128) void bnw_kernel(const float* __restrict__ gamma,
                                                  const float* __restrict__ beta)
{
    const int col = blockIdx.x;
    const int b   = threadIdx.x;
    float x = g_wout[b * DE + col];

    __shared__ float ssum[4], ssq[4];
    __shared__ float smu, srs;
    float s = x, sq = x * x;
#pragma unroll
    for (int o = 16; o > 0; o >>= 1) {
        s  += __shfl_down_sync(0xffffffffu, s, o);
        sq += __shfl_down_sync(0xffffffffu, sq, o);
    }
    int w = b >> 5, l = b & 31;
    if (l == 0) { ssum[w] = s; ssq[w] = sq; }
    __syncthreads();
    if (b == 0) {
        float ts = ssum[0] + ssum[1] + ssum[2] + ssum[3];
        float tq = ssq[0]  + ssq[1]  + ssq[2]  + ssq[3];
        float mu  = ts * (1.f / BATCH);
        float var = tq * (1.f / BATCH) - mu * mu;
        smu = mu;
        srs = rsqrtf(var + 1e-5f);
    }
    __syncthreads();
    g_woutbn[b * DE + col] = gamma[col] * (x - smu) * srs + beta[col];
}

// ---------------------------------------------------------------------
// f2prep: g_f2p[(c*40+d)*100 + j] = f2[c*4000 + j*40 + d].
__global__ __launch_bounds__(256) void f2prep(const float* __restrict__ f2)
{
    const int c = blockIdx.x;          // 0..39
    const int t = threadIdx.x;
    for (int i = t; i < DE * RK; i += 256) {   // i = j*40 + d
        int j = i / RK, d = i % RK;
        g_f2p[(c * RK + d) * DE + j] = f2[c * FSTR + i];
    }
}

// ---------------------------------------------------------------------
// uvw: out[bt][lin] = sum_r vec[bt][r] * F[u*4000 + r*40 + w]  (lin=u*40+w)
// f=0: (g_rbn, f0)->g_u0   f=1: (g_e1bn, f1)->g_v1   f=2: (g_e2bn, f3)->g_v3
// grid (50 lin-tiles of 32, 3 factors), block 256 = 32 lin x 8 bt-groups(16).
__global__ __launch_bounds__(256) void uvw_kernel(const float* __restrict__ f0,
                                                  const float* __restrict__ f1,
                                                  const float* __restrict__ f3)
{
    const int f  = blockIdx.y;
    const int L0 = blockIdx.x * 32;
    const float* F   = (f == 0) ? f0 : (f == 1) ? f1 : f3;
    const float* vec = (f == 0) ? g_rbn : (f == 1) ? g_e1bn : g_e2bn;
    float* out = (f == 0) ? g_u0 : (f == 1) ? g_v1 : g_v3;

    __shared__ float vs[DR][132];      // [r][bt], padded
    const int t = threadIdx.x;
    for (int i = t; i < BATCH * DR; i += 256) {   // coalesced read
        int bt = i / DR, r = i % DR;
        vs[r][bt] = vec[i];
    }
    __syncthreads();

    const int lin = L0 + (t & 31);
    const int bt0 = (t >> 5) * 16;
    const int u = lin / RK, w = lin % RK;
    const float* Fp = F + u * FSTR + w;

    float4 a0 = {0,0,0,0}, a1 = {0,0,0,0}, a2 = {0,0,0,0}, a3 = {0,0,0,0};
#pragma unroll 4
    for (int r = 0; r < DR; r++) {
        float fv = Fp[r * RK];
        float4 v0 = *reinterpret_cast<const float4*>(&vs[r][bt0]);
        float4 v1 = *reinterpret_cast<const float4*>(&vs[r][bt0 + 4]);
        float4 v2 = *reinterpret_cast<const float4*>(&vs[r][bt0 + 8]);
        float4 v3 = *reinterpret_cast<const float4*>(&vs[r][bt0 + 12]);
        a0.x += fv * v0.x; a0.y += fv * v0.y; a0.z += fv * v0.z; a0.w += fv * v0.w;
        a1.x += fv * v1.x; a1.y += fv * v1.y; a1.z += fv * v1.z; a1.w += fv * v1.w;
        a2.x += fv * v2.x; a2.y += fv * v2.y; a2.z += fv * v2.z; a2.w += fv * v2.w;
        a3.x += fv * v3.x; a3.y += fv * v3.y; a3.z += fv * v3.z; a3.w += fv * v3.w;
    }
    float acc[16] = {a0.x,a0.y,a0.z,a0.w, a1.x,a1.y,a1.z,a1.w,
                     a2.x,a2.y,a2.z,a2.w, a3.x,a3.y,a3.z,a3.w};
#pragma unroll
    for (int k = 0; k < 16; k++) out[(bt0 + k) * KDIM + lin] = acc[k];
}

// ---------------------------------------------------------------------
// chain: per bt, m2 = u0@v1, q2 from m2 & v3, then wout[j] via coalesced f2p.
__global__ __launch_bounds__(256) void chain_kernel()
{
    const int bt = blockIdx.x;
    const int t  = threadIdx.x;
    __shared__ float u0[KDIM], v1[KDIM], v3[KDIM], m2[KDIM], q2[KDIM];
    __shared__ float wpart[DE];

    {   // coalesced float4 loads of the three precomputed rows
        const float4* su = reinterpret_cast<const float4*>(g_u0 + bt * KDIM);
        const float4* sv = reinterpret_cast<const float4*>(g_v1 + bt * KDIM);
        const float4* sw = reinterpret_cast<const float4*>(g_v3 + bt * KDIM);
        for (int i = t; i < KDIM / 4; i += 256) {
            *reinterpret_cast<float4*>(&u0[i * 4]) = su[i];
            *reinterpret_cast<float4*>(&v1[i * 4]) = sv[i];
            *reinterpret_cast<float4*>(&v3[i * 4]) = sw[i];
        }
    }
    __syncthreads();

    for (int lin = t; lin < KDIM; lin += 256) {
        int a = lin / RK, c = lin % RK;
        float s = 0.f;
#pragma unroll
        for (int b = 0; b < RK; b++) s += u0[a * RK + b] * v1[b * RK + c];
        m2[lin] = s;
    }
    __syncthreads();

    for (int lin = t; lin < KDIM; lin += 256) {
        int c = lin / RK, d = lin % RK;
        float s = 0.f;
#pragma unroll
        for (int a = 0; a < RK; a++) s += m2[a * RK + c] * v3[d * RK + a];
        q2[lin] = s;
    }
    __syncthreads();

    // wout[j] = sum_cd q2[cd] * f2p[cd*100 + j], split cd range over 2 groups
    float s = 0.f; int j = -1, h = 0;
    if (t < 200) {
        j = t % DE; h = t / DE;
        const float* fp = g_f2p + (size_t)h * 800 * DE + j;
        const float* qp = &q2[h * 800];
#pragma unroll 8
        for (int cd = 0; cd < 800; cd++) s += qp[cd] * fp[(size_t)cd * DE];
        if (h == 0) wpart[j] = s;
    }
    __syncthreads();
    if (h == 1) g_wout[bt * DE + j] = wpart[j] + s;
}

// ---------------------------------------------------------------------
// scores (unchanged): entity-tiled [128 x 100] @ [100 x 10000].
#define SC_SMEM ((BATCH * DE + BATCH * 101) * 4)
__global__ __launch_bounds__(256) void scores_kernel(const float* __restrict__ E)
{
    extern __shared__ float sh[];
    float* Wt = sh;
    float* Et = sh + BATCH * DE;
    const int e0 = blockIdx.x * 128;
    const int ne = (NENT - e0 < 128) ? (NENT - e0) : 128;
    const int tid = threadIdx.x;

    for (int idx = tid; idx < BATCH * DE; idx += 256) Wt[idx] = g_woutbn[idx];
    for (int idx = tid; idx < ne * DE; idx += 256) {
        int r = idx / DE, c = idx % DE;
        Et[r * 101 + c] = E[(size_t)e0 * DE + idx];
    }
    __syncthreads();

    const int ty = tid >> 4;
    const int tx = tid & 15;
    float acc[8][8];
#pragma unroll
    for (int i = 0; i < 8; i++)
#pragma unroll
        for (int j = 0; j < 8; j++) acc[i][j] = 0.f;

    for (int i = 0; i < DE; i++) {
        float wb[8], ee[8];
#pragma unroll
        for (int k = 0; k < 8; k++) wb[k] = Wt[(ty + 16 * k) * DE + i];
#pragma unroll
        for (int k = 0; k < 8; k++) ee[k] = Et[(tx + 16 * k) * 101 + i];
#pragma unroll
        for (int kb = 0; kb < 8; kb++)
#pragma unroll
            for (int ke = 0; ke < 8; ke++) acc[kb][ke] += wb[kb] * ee[ke];
    }

#pragma unroll
    for (int kb = 0; kb < 8; kb++) {
        int bt = ty + 16 * kb;
#pragma unroll
        for (int ke = 0; ke < 8; ke++) {
            int e = tx + 16 * ke;
            if (e < ne) g_scores[(size_t)bt * NENT + e0 + e] = acc[kb][ke];
        }
    }
}

// ---------------------------------------------------------------------
__global__ __launch_bounds__(256) void softmax_kernel(float* __restrict__ pred)
{
    const int bt = blockIdx.x;
    const int t  = threadIdx.x;
    const float* row = g_scores + (size_t)bt * NENT;
    __shared__ float red[8];
    __shared__ float smx, ssumv;

    float mx = -1e30f;
    for (int e = t; e < NENT; e += 256) mx = fmaxf(mx, row[e]);
#pragma unroll
    for (int o = 16; o > 0; o >>= 1) mx = fmaxf(mx, __shfl_xor_sync(0xffffffffu, mx, o));
    if ((t & 31) == 0) red[t >> 5] = mx;
    __syncthreads();
    if (t == 0) {
        float m = red[0];
        for (int i = 1; i < 8; i++) m = fmaxf(m, red[i]);
        smx = m;
    }
    __syncthreads();
    mx = smx;

    float sum = 0.f;
    for (int e = t; e < NENT; e += 256) sum += expf(row[e] - mx);
#pragma unroll
    for (int o = 16; o > 0; o >>= 1) sum += __shfl_xor_sync(0xffffffffu, sum, o);
    __syncthreads();
    if ((t & 31) == 0) red[t >> 5] = sum;
    __syncthreads();
    if (t == 0) {
        float s = 0.f;
        for (int i = 0; i < 8; i++) s += red[i];
        ssumv = s;
    }
    __syncthreads();
    const float inv = 1.f / ssumv;
    for (int e = t; e < NENT; e += 256)
        pred[(size_t)bt * NENT + e] = expf(row[e] - mx) * inv;
}

// ---------------------------------------------------------------------
extern "C" void kernel_launch(void* const* d_in, const int* in_sizes, int n_in,
                              void* d_out, int out_size)
{
    const float* E     = (const float*)d_in[0];
    const float* R     = (const float*)d_in[1];
    const float* f0    = (const float*)d_in[2];
    const float* f1    = (const float*)d_in[3];
    const float* f2    = (const float*)d_in[4];
    const float* f3    = (const float*)d_in[5];
    const float* bnr_g = (const float*)d_in[6];
    const float* bnr_b = (const float*)d_in[7];
    const float* bne_g = (const float*)d_in[8];
    const float* bne_b = (const float*)d_in[9];
    const float* bnw_g = (const float*)d_in[10];
    const float* bnw_b = (const float*)d_in[11];
    const int*   r_idx = (const int*)d_in[12];
    const int*   e_idx1 = (const int*)d_in[13];
    const int*   e_idx2 = (const int*)d_in[14];

    float* outPred = (float*)d_out;                   // [128, 10000]
    float* outW    = outPred + (size_t)BATCH * NENT;  // [100^4]

    cudaFuncSetAttribute(tn_gemm, cudaFuncAttributeMaxDynamicSharedMemorySize, SMEM_TOTAL);
    cudaFuncSetAttribute(scores_kernel, cudaFuncAttributeMaxDynamicSharedMemorySize, SC_SMEM);

    pair_contract<<<MN, 256>>>(f0, f1, 0);
    pair_contract<<<MN, 256>>>(f2, f3, 1);
    bn3_kernel<<<DR + 2 * DE, 128>>>(R, E, r_idx, e_idx1, e_idx2,
                                     bnr_g, bnr_b, bne_g, bne_b);
    f2prep<<<RK, 256>>>(f2);
    uvw_kernel<<<dim3(50, 3), 256>>>(f0, f1, f3);
    dim3 grid((MN + BN - 1) / BN, (MN + BM - 1) / BM);   // 79 x 79
    tn_gemm<<<grid, 256, SMEM_TOTAL>>>(outW);
    chain_kernel<<<BATCH, 256>>>();
    bnw_kernel<<<DE, 128>>>(bnw_g, bnw_b);
    scores_kernel<<<(NENT + 127) / 128, 256, SC_SMEM>>>(E);
    softmax_kernel<<<BATCH, 256>>>(outPred);
}